// round 15
// baseline (speedup 1.0000x reference)
#include <cuda_runtime.h>
#include <cuda_bf16.h>
#include <math.h>
#include <stdint.h>

#define C 128
#define BMAX 4096
#define NMAX 500000

// ---------------- device scratch (no allocations allowed) -------------------
__device__ __align__(16) __nv_bfloat16 g_Wh2[512 * 256];  // reordered folded W [col][256K], hi
__device__ __align__(16) __nv_bfloat16 g_Wl2[512 * 256];  // lo split
__device__ __align__(16) __nv_bfloat16 g_W0h[512 * 128];  // reordered W_hh (iter0), hi
__device__ __align__(16) __nv_bfloat16 g_W0l[512 * 128];
__device__ __align__(16) __nv_bfloat16 g_Ah0[BMAX * 128]; // h0 splits (iter0 A)
__device__ __align__(16) __nv_bfloat16 g_Al0[BMAX * 128];
__device__ __align__(16) __nv_bfloat16 g_Hh[BMAX * 128];  // h(t) splits (partial-GEMM A)
__device__ __align__(16) __nv_bfloat16 g_Hl[BMAX * 128];
__device__ __align__(16) __nv_bfloat16 g_Rh[BMAX * 128];  // r(t) splits (r-GEMM A)
__device__ __align__(16) __nv_bfloat16 g_Rl[BMAX * 128];
__device__ __align__(16) float g_P[BMAX * 512];           // partial Wh'*h (reordered cols)
__device__ __align__(16) float g_q[BMAX * 128];           // h (fp32) for attention
__device__ __align__(16) float g_c[BMAX * 128];           // LSTM cell state
__device__ __align__(16) float g_e[NMAX];                 // logits scratch
__device__ __align__(16) float g_bias2[512];              // reordered bias
__device__ int g_seg[BMAX + 1];

__device__ __forceinline__ float sigf(float x) { return 1.0f / (1.0f + __expf(-x)); }

// ---------------- merged prep: weights + h0 convert + seg offsets ----------
__device__ __forceinline__ int bload(const int* p, int i, int is64) {
    return is64 ? p[2 * i] : p[i];
}
__global__ void prep_all(const float* __restrict__ Wih, const float* __restrict__ Whh,
                         const float* __restrict__ bih, const float* __restrict__ bhh,
                         const float* __restrict__ h, const int* __restrict__ batch,
                         int N, int B) {
    int idx = blockIdx.x * blockDim.x + threadIdx.x;

    if (idx < 512 * 256) {       // weights: col = 4*ch + gate; n = gate*C + ch
        int col = idx >> 8;
        int kk  = idx & 255;
        int gate = col & 3, ch = col >> 2;
        int n = gate * C + ch;
        float w = Wih[n * 256 + kk] + (kk < C ? Whh[n * C + kk] : 0.0f);
        __nv_bfloat16 hi = __float2bfloat16(w);
        g_Wh2[col * 256 + kk] = hi;
        g_Wl2[col * 256 + kk] = __float2bfloat16(w - __bfloat162float(hi));
        if (kk < C) {
            float w0 = Whh[n * C + kk];
            __nv_bfloat16 h0 = __float2bfloat16(w0);
            g_W0h[col * C + kk] = h0;
            g_W0l[col * C + kk] = __float2bfloat16(w0 - __bfloat162float(h0));
        }
        if (kk == 0) g_bias2[col] = bih[n] + bhh[n];
    }
    if (idx < B * C) {           // h0 -> bf16 splits
        float x = h[idx];
        __nv_bfloat16 hi = __float2bfloat16(x);
        g_Ah0[idx] = hi;
        g_Al0[idx] = __float2bfloat16(x - __bfloat162float(hi));
    }
    if (idx <= N) {              // segment offsets (int32/int64 probe)
        const int is64 = (batch[N - 1] == 0);
        if (idx == 0) {
            int b0 = bload(batch, 0, is64);
            for (int b = 0; b <= b0; b++) g_seg[b] = 0;
        } else if (idx == N) {
            int bl = bload(batch, N - 1, is64);
            for (int b = bl + 1; b <= B; b++) g_seg[b] = N;
        } else {
            int bc = bload(batch, idx, is64), bp = bload(batch, idx - 1, is64);
            for (int b = bp + 1; b <= bc; b++) g_seg[b] = idx;
        }
    }
}

// ---------------- mma.sync bf16 GEMM (3 modes) ------------------------------
// mode 0: gates = W0 * h0            + LSTM(first)           (iter 0)
// mode 1: gates = Wr * r + P + bias  + LSTM                   (iters 1..3)
// mode 2: P     = Wh' * h                     (no epilogue; overlapped w/ attn)
// CTA tile 64(M) x 64(N), 128 thr (4 warps, 32x32). K=128 in 4 chunks, 3-stage ring.
#define ROWB 80
#define TILE_SPLIT (64 * ROWB)
#define OFF_AH 0
#define OFF_AL TILE_SPLIT
#define OFF_BH (2 * TILE_SPLIT)
#define OFF_BL (3 * TILE_SPLIT)
#define STAGE_BYTES (4 * TILE_SPLIT)             // 20480
#define NSTG 3
#define DYN_BYTES (NSTG * STAGE_BYTES)           // 61440
#define PATCH_STRIDE 36
#define PATCH_BYTES (32 * PATCH_STRIDE * 4)
#define NC 4

__device__ __forceinline__ void cpa16(uint32_t dst, const void* src) {
    asm volatile("cp.async.cg.shared.global [%0], [%1], 16;" :: "r"(dst), "l"(src));
}
#define CP_COMMIT() asm volatile("cp.async.commit_group;" ::: "memory")
#define CP_WAIT1()  asm volatile("cp.async.wait_group 1;" ::: "memory")

__device__ __forceinline__ void mma16816(float* c, const uint32_t* a, uint32_t b0, uint32_t b1) {
    asm volatile(
        "mma.sync.aligned.m16n8k16.row.col.f32.bf16.bf16.f32 "
        "{%0,%1,%2,%3}, {%4,%5,%6,%7}, {%8,%9}, {%0,%1,%2,%3};"
        : "+f"(c[0]), "+f"(c[1]), "+f"(c[2]), "+f"(c[3])
        : "r"(a[0]), "r"(a[1]), "r"(a[2]), "r"(a[3]), "r"(b0), "r"(b1));
}

__global__ __launch_bounds__(128, 3)
void gemm_fused(const float* __restrict__ h_ext, int mode) {
    extern __shared__ char dyn[];
    __shared__ float sbias[64];

    // resolve scratch pointers IN DEVICE CODE (host-side symbol refs are UB)
    const __nv_bfloat16 *Ah, *Al, *Bh, *Bl;
    int strideB;
    if (mode == 0)      { Ah = g_Ah0; Al = g_Al0; Bh = g_W0h;       Bl = g_W0l;       strideB = 128; }
    else if (mode == 1) { Ah = g_Rh;  Al = g_Rl;  Bh = g_Wh2 + 128; Bl = g_Wl2 + 128; strideB = 256; }
    else                { Ah = g_Hh;  Al = g_Hl;  Bh = g_Wh2;       Bl = g_Wl2;       strideB = 256; }

    const int tid = threadIdx.x, wid = tid >> 5, lane = tid & 31;
    const int g = lane >> 2, t = lane & 3;
    const int bn = blockIdx.x;             // 0..7 (64 reordered cols)
    const int bm = blockIdx.y;             // 0..63
    const int m0 = bm * 64;
    const int wm = (wid >> 1) * 32;
    const int wn = (wid & 1) * 32;

    if (tid < 64) sbias[tid] = g_bias2[bn * 64 + tid];

    const __nv_bfloat16* Abh = Ah + (size_t)m0 * 128;
    const __nv_bfloat16* Abl = Al + (size_t)m0 * 128;
    const __nv_bfloat16* Bbh = Bh + (size_t)(bn * 64) * strideB;
    const __nv_bfloat16* Bbl = Bl + (size_t)(bn * 64) * strideB;

    const uint32_t sbase = (uint32_t)__cvta_generic_to_shared(dyn);

    auto issue_chunk = [&](int cch, int s) {
        uint32_t st = sbase + s * STAGE_BYTES;
#pragma unroll
        for (int i = tid; i < 256; i += 128) {
            int row = i >> 2, seg = i & 3;
            uint32_t dst = row * ROWB + seg * 16;
            size_t srcA = (size_t)row * 128 + cch * 32 + seg * 8;
            size_t srcB = (size_t)row * strideB + cch * 32 + seg * 8;
            cpa16(st + OFF_AH + dst, Abh + srcA);
            cpa16(st + OFF_AL + dst, Abl + srcA);
            cpa16(st + OFF_BH + dst, Bbh + srcB);
            cpa16(st + OFF_BL + dst, Bbl + srcB);
        }
    };

    issue_chunk(0, 0); CP_COMMIT();
    issue_chunk(1, 1); CP_COMMIT();

    float acc[2][4][4];
#pragma unroll
    for (int mi = 0; mi < 2; mi++)
#pragma unroll
        for (int ni = 0; ni < 4; ni++)
#pragma unroll
            for (int e = 0; e < 4; e++) acc[mi][ni][e] = 0.0f;

    int sc = 0;
    for (int c = 0; c < NC; c++) {
        CP_WAIT1();
        __syncthreads();
        const char* st = dyn + sc * STAGE_BYTES;

#pragma unroll
        for (int ks = 0; ks < 2; ks++) {
            uint32_t ah[2][4], al[2][4];
            const int kb = ks * 32 + t * 4;
#pragma unroll
            for (int mi = 0; mi < 2; mi++) {
                int r0 = (wm + mi * 16 + g) * ROWB + kb;
                int r1 = r0 + 8 * ROWB;
                ah[mi][0] = *(const uint32_t*)(st + OFF_AH + r0);
                ah[mi][1] = *(const uint32_t*)(st + OFF_AH + r1);
                ah[mi][2] = *(const uint32_t*)(st + OFF_AH + r0 + 16);
                ah[mi][3] = *(const uint32_t*)(st + OFF_AH + r1 + 16);
                al[mi][0] = *(const uint32_t*)(st + OFF_AL + r0);
                al[mi][1] = *(const uint32_t*)(st + OFF_AL + r1);
                al[mi][2] = *(const uint32_t*)(st + OFF_AL + r0 + 16);
                al[mi][3] = *(const uint32_t*)(st + OFF_AL + r1 + 16);
            }
#pragma unroll
            for (int ni = 0; ni < 4; ni++) {
                int nrow = (wn + ni * 8 + g) * ROWB + kb;
                uint32_t bh0 = *(const uint32_t*)(st + OFF_BH + nrow);
                uint32_t bh1 = *(const uint32_t*)(st + OFF_BH + nrow + 16);
                uint32_t bl0 = *(const uint32_t*)(st + OFF_BL + nrow);
                uint32_t bl1 = *(const uint32_t*)(st + OFF_BL + nrow + 16);
#pragma unroll
                for (int mi = 0; mi < 2; mi++) {
                    mma16816(acc[mi][ni], ah[mi], bh0, bh1);
                    mma16816(acc[mi][ni], al[mi], bh0, bh1);
                    mma16816(acc[mi][ni], ah[mi], bl0, bl1);
                }
            }
        }
        int cn = c + 2;
        if (cn < NC) {
            int sn = sc + 2; if (sn >= NSTG) sn -= NSTG;
            issue_chunk(cn, sn);
        }
        CP_COMMIT();
        if (++sc == NSTG) sc = 0;
    }

    if (mode == 2) {
        // direct store of partial to g_P (reordered col space)
#pragma unroll
        for (int mi = 0; mi < 2; mi++)
#pragma unroll
            for (int ni = 0; ni < 4; ni++) {
                int pr = m0 + wm + mi * 16 + g;
                int pc = bn * 64 + wn + ni * 8 + 2 * t;
                *(float2*)&g_P[(size_t)pr * 512 + pc]       = make_float2(acc[mi][ni][0], acc[mi][ni][1]);
                *(float2*)&g_P[(size_t)(pr + 8) * 512 + pc] = make_float2(acc[mi][ni][2], acc[mi][ni][3]);
            }
        return;
    }

    __syncthreads();
    // ---- dump acc to per-warp patch [32][36] floats (fits in stage 0) ----
    float* patch = (float*)(dyn + wid * PATCH_BYTES);
#pragma unroll
    for (int mi = 0; mi < 2; mi++)
#pragma unroll
        for (int ni = 0; ni < 4; ni++) {
            int pr = mi * 16 + g, pc = ni * 8 + 2 * t;
            *(float2*)&patch[pr * PATCH_STRIDE + pc]       = make_float2(acc[mi][ni][0], acc[mi][ni][1]);
            *(float2*)&patch[(pr + 8) * PATCH_STRIDE + pc] = make_float2(acc[mi][ni][2], acc[mi][ni][3]);
        }
    __syncthreads();

    // ---- fused LSTM: 64 rows x 16 channels per CTA = 1024 items ----
    const int first = (mode == 0);
#pragma unroll
    for (int it = 0; it < 8; it++) {
        int item = tid + it * 128;
        int r = item >> 4, chl = item & 15;
        int w = (r >> 5) * 2 + (chl >> 3);
        const float* p = (const float*)(dyn + w * PATCH_BYTES)
                         + (r & 31) * PATCH_STRIDE + (chl & 7) * 4;
        float4 gv = *(const float4*)p;
        int cb = chl * 4;
        int row = m0 + r;
        float4 pv = make_float4(0.f, 0.f, 0.f, 0.f);
        if (mode == 1) pv = *(const float4*)&g_P[(size_t)row * 512 + bn * 64 + cb];
        float gi = gv.x + pv.x + sbias[cb + 0];
        float gf = gv.y + pv.y + sbias[cb + 1];
        float gg = gv.z + pv.z + sbias[cb + 2];
        float go = gv.w + pv.w + sbias[cb + 3];
        int ch = bn * 16 + chl;
        size_t cidx = (size_t)row * C + ch;
        float cp = first ? h_ext[cidx] : g_c[cidx];
        float cn = sigf(gf) * cp + sigf(gi) * tanhf(gg);
        g_c[cidx] = cn;
        float hn = sigf(go) * tanhf(cn);
        g_q[cidx] = hn;
        __nv_bfloat16 hh = __float2bfloat16(hn);
        g_Hh[cidx] = hh;
        g_Hl[cidx] = __float2bfloat16(hn - __bfloat162float(hh));
    }
}

// ---------------- segment attention: one block (256 thr) per segment --------
__global__ __launch_bounds__(256)
void attn_kernel(const float* __restrict__ kmat, const float* __restrict__ vmat,
                 float* __restrict__ out, int iter) {
    int b = blockIdx.x;
    int tid = threadIdx.x;
    int lane = tid & 31;
    int w = tid >> 5;                       // 8 warps
    int start = g_seg[b], end = g_seg[b + 1];

    float4 q4 = *(const float4*)(g_q + (size_t)b * C + lane * 4);

    __shared__ float smax[8];
    __shared__ float ssum[8];
    __shared__ __align__(16) float sr[8][C];

    // pass 1: logits + max
    float wmax = -INFINITY;
    int node = start + w;
    for (; node + 8 < end; node += 16) {
        float4 ka = *(const float4*)(kmat + (size_t)node * C + lane * 4);
        float4 kb = *(const float4*)(kmat + (size_t)(node + 8) * C + lane * 4);
        float da = ka.x * q4.x + ka.y * q4.y + ka.z * q4.z + ka.w * q4.w;
        float db = kb.x * q4.x + kb.y * q4.y + kb.z * q4.z + kb.w * q4.w;
#pragma unroll
        for (int off = 16; off > 0; off >>= 1) {
            da += __shfl_xor_sync(0xFFFFFFFFu, da, off);
            db += __shfl_xor_sync(0xFFFFFFFFu, db, off);
        }
        if (lane == 0) { g_e[node] = da; g_e[node + 8] = db; }
        wmax = fmaxf(wmax, fmaxf(da, db));
    }
    for (; node < end; node += 8) {
        float4 ka = *(const float4*)(kmat + (size_t)node * C + lane * 4);
        float da = ka.x * q4.x + ka.y * q4.y + ka.z * q4.z + ka.w * q4.w;
#pragma unroll
        for (int off = 16; off > 0; off >>= 1)
            da += __shfl_xor_sync(0xFFFFFFFFu, da, off);
        if (lane == 0) g_e[node] = da;
        wmax = fmaxf(wmax, da);
    }
    if (lane == 0) smax[w] = wmax;
    __syncthreads();

    float m = -INFINITY;
#pragma unroll
    for (int i = 0; i < 8; i++) m = fmaxf(m, smax[i]);

    // pass 2: exp + weighted V sum
    float s = 0.0f;
    float4 r4 = make_float4(0.f, 0.f, 0.f, 0.f);
    for (node = start + w; node < end; node += 8) {
        float a = __expf(g_e[node] - m);
        float4 v4 = *(const float4*)(vmat + (size_t)node * C + lane * 4);
        s += a;
        r4.x = fmaf(a, v4.x, r4.x); r4.y = fmaf(a, v4.y, r4.y);
        r4.z = fmaf(a, v4.z, r4.z); r4.w = fmaf(a, v4.w, r4.w);
    }
    if (lane == 0) ssum[w] = s;
    *(float4*)(&sr[w][lane * 4]) = r4;
    __syncthreads();

    if (tid < C) {
        float stot = 0.0f, rc = 0.0f;
#pragma unroll
        for (int i = 0; i < 8; i++) { stot += ssum[i]; rc += sr[i][tid]; }
        float val = rc / (stot + 1e-16f);
        out[(size_t)b * 4 * C + iter * C + tid] = val;       // readout
        __nv_bfloat16 hv = __float2bfloat16(val);            // r splits for next r-GEMM
        g_Rh[(size_t)b * C + tid] = hv;
        g_Rl[(size_t)b * C + tid] = __float2bfloat16(val - __bfloat162float(hv));
    }
}

// ---------------- launch -----------------------------------------------------
extern "C" void kernel_launch(void* const* d_in, const int* in_sizes, int n_in,
                              void* d_out, int out_size) {
    const float* k     = (const float*)d_in[0];
    const float* v     = (const float*)d_in[1];
    const float* h     = (const float*)d_in[2];
    const float* W_ih  = (const float*)d_in[3];
    const float* W_hh  = (const float*)d_in[4];
    const float* b_ih  = (const float*)d_in[5];
    const float* b_hh  = (const float*)d_in[6];
    const int*   batch = (const int*)d_in[7];
    float* out = (float*)d_out;

    int N = in_sizes[0] / C;
    int B = in_sizes[2] / C;

    static cudaStream_t s2 = nullptr;
    static cudaEvent_t evA[3], evB[3];
    if (!s2) {
        cudaStreamCreateWithFlags(&s2, cudaStreamNonBlocking);
        for (int i = 0; i < 3; i++) {
            cudaEventCreateWithFlags(&evA[i], cudaEventDisableTiming);
            cudaEventCreateWithFlags(&evB[i], cudaEventDisableTiming);
        }
    }

    cudaFuncSetAttribute(gemm_fused, cudaFuncAttributeMaxDynamicSharedMemorySize, DYN_BYTES);

    int prep_items = (B * C > N + 1) ? B * C : N + 1;   // covers 512*256 too
    prep_all<<<(prep_items + 255) / 256, 256>>>(W_ih, W_hh, b_ih, b_hh, h, batch, N, B);

    // iter 0 GEMM (h-only path)
    gemm_fused<<<dim3(8, B / 64), 128, DYN_BYTES>>>(h, 0);

    for (int t = 0; t < 4; t++) {
        if (t < 3) {
            // fork: partial P(t+1) = Wh' * h(t) on side stream, concurrent with attn(t)
            cudaEventRecord(evA[t], 0);
            cudaStreamWaitEvent(s2, evA[t], 0);
            gemm_fused<<<dim3(8, B / 64), 128, DYN_BYTES, s2>>>(h, 2);
            cudaEventRecord(evB[t], s2);
        }
        attn_kernel<<<B, 256>>>(k, v, out, t);
        if (t < 3) {
            cudaStreamWaitEvent(0, evB[t], 0);   // join before r-GEMM
            gemm_fused<<<dim3(8, B / 64), 128, DYN_BYTES>>>(h, 1);
        }
    }
}

// round 16
// speedup vs baseline: 1.1457x; 1.1457x over previous
#include <cuda_runtime.h>
#include <cuda_bf16.h>
#include <math.h>
#include <stdint.h>

#define C 128
#define BMAX 4096
#define NMAX 500000

// ---------------- device scratch (no allocations allowed) -------------------
__device__ __align__(16) __nv_bfloat16 g_Wh2[512 * 256];  // reordered folded W, hi split
__device__ __align__(16) __nv_bfloat16 g_Wl2[512 * 256];  // lo split
__device__ __align__(16) __nv_bfloat16 g_W0h[512 * 128];  // reordered W_hh (iter0), hi
__device__ __align__(16) __nv_bfloat16 g_W0l[512 * 128];
__device__ __align__(16) __nv_bfloat16 g_Ah0[BMAX * 128]; // h0 splits (iter0 A)
__device__ __align__(16) __nv_bfloat16 g_Al0[BMAX * 128];
__device__ __align__(16) __nv_bfloat16 g_Xh0[BMAX * 256]; // ping-pong [h | r] hi split
__device__ __align__(16) __nv_bfloat16 g_Xl0[BMAX * 256];
__device__ __align__(16) __nv_bfloat16 g_Xh1[BMAX * 256];
__device__ __align__(16) __nv_bfloat16 g_Xl1[BMAX * 256];
__device__ __align__(16) float g_q[BMAX * 128];           // h (fp32) for attention
__device__ __align__(16) float g_c[BMAX * 128];           // LSTM cell state
__device__ __align__(16) float g_e[NMAX];                 // logits scratch
__device__ __align__(16) float g_bias2[512];              // reordered bias
__device__ int g_seg[BMAX + 1];

__device__ __forceinline__ float sigf(float x) { return 1.0f / (1.0f + __expf(-x)); }

// ---------------- merged prep: weights + h0 convert + seg offsets ----------
__device__ __forceinline__ int bload(const int* p, int i, int is64) {
    return is64 ? p[2 * i] : p[i];
}
__global__ void prep_all(const float* __restrict__ Wih, const float* __restrict__ Whh,
                         const float* __restrict__ bih, const float* __restrict__ bhh,
                         const float* __restrict__ h, const int* __restrict__ batch,
                         int N, int B) {
    int idx = blockIdx.x * blockDim.x + threadIdx.x;

    if (idx < 512 * 256) {       // weights: col = 4*ch + gate; n = gate*C + ch
        int col = idx >> 8;
        int kk  = idx & 255;
        int gate = col & 3, ch = col >> 2;
        int n = gate * C + ch;
        float w = Wih[n * 256 + kk] + (kk < C ? Whh[n * C + kk] : 0.0f);
        __nv_bfloat16 hi = __float2bfloat16(w);
        g_Wh2[col * 256 + kk] = hi;
        g_Wl2[col * 256 + kk] = __float2bfloat16(w - __bfloat162float(hi));
        if (kk < C) {
            float w0 = Whh[n * C + kk];
            __nv_bfloat16 h0 = __float2bfloat16(w0);
            g_W0h[col * C + kk] = h0;
            g_W0l[col * C + kk] = __float2bfloat16(w0 - __bfloat162float(h0));
        }
        if (kk == 0) g_bias2[col] = bih[n] + bhh[n];
    }
    if (idx < B * C) {           // h0 -> bf16 splits
        float x = h[idx];
        __nv_bfloat16 hi = __float2bfloat16(x);
        g_Ah0[idx] = hi;
        g_Al0[idx] = __float2bfloat16(x - __bfloat162float(hi));
    }
    if (idx <= N) {              // segment offsets (int32/int64 probe)
        const int is64 = (batch[N - 1] == 0);
        if (idx == 0) {
            int b0 = bload(batch, 0, is64);
            for (int b = 0; b <= b0; b++) g_seg[b] = 0;
        } else if (idx == N) {
            int bl = bload(batch, N - 1, is64);
            for (int b = bl + 1; b <= B; b++) g_seg[b] = N;
        } else {
            int bc = bload(batch, idx, is64), bp = bload(batch, idx - 1, is64);
            for (int b = bp + 1; b <= bc; b++) g_seg[b] = idx;
        }
    }
}

// ---------------- mma.sync bf16 GEMM + fused LSTM epilogue ------------------
// CTA tile: 64(M) x 64(N), 128 threads (4 warps, warp tile 32x32).
// K chunked by 32, 3-stage cp.async ring (depth-2 prefetch). 3-term bf16 split.
#define ROWB 80
#define TILE_SPLIT (64 * ROWB)
#define OFF_AH 0
#define OFF_AL TILE_SPLIT
#define OFF_BH (2 * TILE_SPLIT)
#define OFF_BL (3 * TILE_SPLIT)
#define STAGE_BYTES (4 * TILE_SPLIT)             // 20480
#define NSTG 3
#define DYN_BYTES (NSTG * STAGE_BYTES)           // 61440
#define PATCH_STRIDE 36
#define PATCH_BYTES (32 * PATCH_STRIDE * 4)

__device__ __forceinline__ void cpa16(uint32_t dst, const void* src) {
    asm volatile("cp.async.cg.shared.global [%0], [%1], 16;" :: "r"(dst), "l"(src));
}
#define CP_COMMIT() asm volatile("cp.async.commit_group;" ::: "memory")
#define CP_WAIT1()  asm volatile("cp.async.wait_group 1;" ::: "memory")

__device__ __forceinline__ void mma16816(float* c, const uint32_t* a, uint32_t b0, uint32_t b1) {
    asm volatile(
        "mma.sync.aligned.m16n8k16.row.col.f32.bf16.bf16.f32 "
        "{%0,%1,%2,%3}, {%4,%5,%6,%7}, {%8,%9}, {%0,%1,%2,%3};"
        : "+f"(c[0]), "+f"(c[1]), "+f"(c[2]), "+f"(c[3])
        : "r"(a[0]), "r"(a[1]), "r"(a[2]), "r"(a[3]), "r"(b0), "r"(b1));
}

__global__ __launch_bounds__(128, 3)
void gemm_fused(const float* __restrict__ h_ext, int first, int NC, int cur, int nxt) {
    extern __shared__ char dyn[];
    __shared__ float sbias[64];

    const __nv_bfloat16 *Ah, *Al, *Bh, *Bl;
    if (first)         { Ah = g_Ah0; Al = g_Al0; Bh = g_W0h; Bl = g_W0l; }
    else if (cur == 0) { Ah = g_Xh0; Al = g_Xl0; Bh = g_Wh2; Bl = g_Wl2; }
    else               { Ah = g_Xh1; Al = g_Xl1; Bh = g_Wh2; Bl = g_Wl2; }
    __nv_bfloat16* XhO = nxt ? g_Xh1 : g_Xh0;
    __nv_bfloat16* XlO = nxt ? g_Xl1 : g_Xl0;

    const int tid = threadIdx.x, wid = tid >> 5, lane = tid & 31;
    const int g = lane >> 2, t = lane & 3;
    const int bn = blockIdx.x;
    const int bm = blockIdx.y;
    const int m0 = bm * 64;
    const int wm = (wid >> 1) * 32;
    const int wn = (wid & 1) * 32;

    if (tid < 64) sbias[tid] = g_bias2[bn * 64 + tid];

    const int strideK = NC * 32;
    const __nv_bfloat16* Abh = Ah + (size_t)m0 * strideK;
    const __nv_bfloat16* Abl = Al + (size_t)m0 * strideK;
    const __nv_bfloat16* Bbh = Bh + (size_t)(bn * 64) * strideK;
    const __nv_bfloat16* Bbl = Bl + (size_t)(bn * 64) * strideK;

    const uint32_t sbase = (uint32_t)__cvta_generic_to_shared(dyn);

    auto issue_chunk = [&](int cch, int s) {
        uint32_t st = sbase + s * STAGE_BYTES;
#pragma unroll
        for (int i = tid; i < 256; i += 128) {
            int row = i >> 2, seg = i & 3;
            uint32_t dst = row * ROWB + seg * 16;
            size_t src = (size_t)row * strideK + cch * 32 + seg * 8;
            cpa16(st + OFF_AH + dst, Abh + src);
            cpa16(st + OFF_AL + dst, Abl + src);
            cpa16(st + OFF_BH + dst, Bbh + src);
            cpa16(st + OFF_BL + dst, Bbl + src);
        }
    };

    issue_chunk(0, 0); CP_COMMIT();
    issue_chunk(1, 1); CP_COMMIT();

    float acc[2][4][4];
#pragma unroll
    for (int mi = 0; mi < 2; mi++)
#pragma unroll
        for (int ni = 0; ni < 4; ni++)
#pragma unroll
            for (int e = 0; e < 4; e++) acc[mi][ni][e] = 0.0f;

    int sc = 0;
    for (int c = 0; c < NC; c++) {
        CP_WAIT1();
        __syncthreads();
        const char* st = dyn + sc * STAGE_BYTES;

#pragma unroll
        for (int ks = 0; ks < 2; ks++) {
            uint32_t ah[2][4], al[2][4];
            const int kb = ks * 32 + t * 4;
#pragma unroll
            for (int mi = 0; mi < 2; mi++) {
                int r0 = (wm + mi * 16 + g) * ROWB + kb;
                int r1 = r0 + 8 * ROWB;
                ah[mi][0] = *(const uint32_t*)(st + OFF_AH + r0);
                ah[mi][1] = *(const uint32_t*)(st + OFF_AH + r1);
                ah[mi][2] = *(const uint32_t*)(st + OFF_AH + r0 + 16);
                ah[mi][3] = *(const uint32_t*)(st + OFF_AH + r1 + 16);
                al[mi][0] = *(const uint32_t*)(st + OFF_AL + r0);
                al[mi][1] = *(const uint32_t*)(st + OFF_AL + r1);
                al[mi][2] = *(const uint32_t*)(st + OFF_AL + r0 + 16);
                al[mi][3] = *(const uint32_t*)(st + OFF_AL + r1 + 16);
            }
#pragma unroll
            for (int ni = 0; ni < 4; ni++) {
                int nrow = (wn + ni * 8 + g) * ROWB + kb;
                uint32_t bh0 = *(const uint32_t*)(st + OFF_BH + nrow);
                uint32_t bh1 = *(const uint32_t*)(st + OFF_BH + nrow + 16);
                uint32_t bl0 = *(const uint32_t*)(st + OFF_BL + nrow);
                uint32_t bl1 = *(const uint32_t*)(st + OFF_BL + nrow + 16);
#pragma unroll
                for (int mi = 0; mi < 2; mi++) {
                    mma16816(acc[mi][ni], ah[mi], bh0, bh1);
                    mma16816(acc[mi][ni], al[mi], bh0, bh1);
                    mma16816(acc[mi][ni], ah[mi], bl0, bl1);
                }
            }
        }
        int cn = c + 2;
        if (cn < NC) {
            int sn = sc + 2; if (sn >= NSTG) sn -= NSTG;
            issue_chunk(cn, sn);
        }
        CP_COMMIT();
        if (++sc == NSTG) sc = 0;
    }
    __syncthreads();

    // ---- dump acc to per-warp patch [32][36] floats (fits in stage 0) ----
    float* patch = (float*)(dyn + wid * PATCH_BYTES);
#pragma unroll
    for (int mi = 0; mi < 2; mi++)
#pragma unroll
        for (int ni = 0; ni < 4; ni++) {
            int pr = mi * 16 + g, pc = ni * 8 + 2 * t;
            *(float2*)&patch[pr * PATCH_STRIDE + pc]       = make_float2(acc[mi][ni][0], acc[mi][ni][1]);
            *(float2*)&patch[(pr + 8) * PATCH_STRIDE + pc] = make_float2(acc[mi][ni][2], acc[mi][ni][3]);
        }
    __syncthreads();

    // ---- fused LSTM: 64 rows x 16 channels per CTA = 1024 items ----
#pragma unroll
    for (int it = 0; it < 8; it++) {
        int item = tid + it * 128;
        int r = item >> 4, chl = item & 15;
        int w = (r >> 5) * 2 + (chl >> 3);
        const float* p = (const float*)(dyn + w * PATCH_BYTES)
                         + (r & 31) * PATCH_STRIDE + (chl & 7) * 4;
        float4 gv = *(const float4*)p;
        int cb = chl * 4;
        float gi = gv.x + sbias[cb + 0];
        float gf = gv.y + sbias[cb + 1];
        float gg = gv.z + sbias[cb + 2];
        float go = gv.w + sbias[cb + 3];
        int row = m0 + r;
        int ch = bn * 16 + chl;
        size_t cidx = (size_t)row * C + ch;
        float cp = first ? h_ext[cidx] : g_c[cidx];
        float cn = sigf(gf) * cp + sigf(gi) * tanhf(gg);
        g_c[cidx] = cn;
        float hn = sigf(go) * tanhf(cn);
        g_q[cidx] = hn;
        __nv_bfloat16 hh = __float2bfloat16(hn);
        XhO[(size_t)row * 256 + ch] = hh;
        XlO[(size_t)row * 256 + ch] = __float2bfloat16(hn - __bfloat162float(hh));
    }
}

// ---------------- segment attention: one block (256 thr) per segment --------
// Pass 1: 8-lane-per-row groups (4 rows/warp/iter, 3-level oct reduction).
// Pass 2: 1 row/warp, unroll 2.
__global__ __launch_bounds__(256)
void attn_kernel(const float* __restrict__ kmat, const float* __restrict__ vmat,
                 float* __restrict__ out, int iter, int nxt) {
    int b = blockIdx.x;
    int tid = threadIdx.x;
    int lane = tid & 31;
    int w = tid >> 5;                       // 8 warps
    int start = g_seg[b], end = g_seg[b + 1];

    __nv_bfloat16* XhO = nxt ? g_Xh1 : g_Xh0;
    __nv_bfloat16* XlO = nxt ? g_Xl1 : g_Xl0;

    __shared__ float smax[8];
    __shared__ float ssum[8];
    __shared__ __align__(16) float sr[8][C];

    // ---- pass 1: 4 rows per warp per iter; lanes 8-per-row ----
    {
        const int sub = lane & 7, rg = lane >> 3;
        const float* qb = g_q + (size_t)b * C + sub * 4;
        float4 q0 = *(const float4*)(qb);
        float4 q1 = *(const float4*)(qb + 32);
        float4 q2 = *(const float4*)(qb + 64);
        float4 q3 = *(const float4*)(qb + 96);

        float wmax = -INFINITY;
        for (int node = start + w * 4; node < end; node += 32) {
            int myrow = node + rg;
            float d = 0.0f;
            bool valid = (myrow < end);
            if (valid) {
                const float* kr = kmat + (size_t)myrow * C + sub * 4;
                float4 a0 = *(const float4*)(kr);
                float4 a1 = *(const float4*)(kr + 32);
                float4 a2 = *(const float4*)(kr + 64);
                float4 a3 = *(const float4*)(kr + 96);
                d  = a0.x * q0.x + a0.y * q0.y + a0.z * q0.z + a0.w * q0.w;
                d += a1.x * q1.x + a1.y * q1.y + a1.z * q1.z + a1.w * q1.w;
                d += a2.x * q2.x + a2.y * q2.y + a2.z * q2.z + a2.w * q2.w;
                d += a3.x * q3.x + a3.y * q3.y + a3.z * q3.z + a3.w * q3.w;
            }
            d += __shfl_xor_sync(0xFFFFFFFFu, d, 4);
            d += __shfl_xor_sync(0xFFFFFFFFu, d, 2);
            d += __shfl_xor_sync(0xFFFFFFFFu, d, 1);
            if (valid) {
                if (sub == 0) g_e[myrow] = d;
                wmax = fmaxf(wmax, d);
            }
        }
#pragma unroll
        for (int off = 16; off > 0; off >>= 1)
            wmax = fmaxf(wmax, __shfl_xor_sync(0xFFFFFFFFu, wmax, off));
        if (lane == 0) smax[w] = wmax;
    }
    __syncthreads();

    float m = -INFINITY;
#pragma unroll
    for (int i = 0; i < 8; i++) m = fmaxf(m, smax[i]);

    // ---- pass 2: exp + weighted V sum (unroll 2) ----
    float s = 0.0f;
    float4 r4 = make_float4(0.f, 0.f, 0.f, 0.f);
    int node = start + w;
    for (; node + 8 < end; node += 16) {
        float e0 = g_e[node], e1 = g_e[node + 8];
        float4 v0 = *(const float4*)(vmat + (size_t)node * C + lane * 4);
        float4 v1 = *(const float4*)(vmat + (size_t)(node + 8) * C + lane * 4);
        float a0 = __expf(e0 - m), a1 = __expf(e1 - m);
        s += a0 + a1;
        r4.x = fmaf(a0, v0.x, fmaf(a1, v1.x, r4.x));
        r4.y = fmaf(a0, v0.y, fmaf(a1, v1.y, r4.y));
        r4.z = fmaf(a0, v0.z, fmaf(a1, v1.z, r4.z));
        r4.w = fmaf(a0, v0.w, fmaf(a1, v1.w, r4.w));
    }
    for (; node < end; node += 8) {
        float a = __expf(g_e[node] - m);
        float4 v4 = *(const float4*)(vmat + (size_t)node * C + lane * 4);
        s += a;
        r4.x = fmaf(a, v4.x, r4.x); r4.y = fmaf(a, v4.y, r4.y);
        r4.z = fmaf(a, v4.z, r4.z); r4.w = fmaf(a, v4.w, r4.w);
    }
    if (lane == 0) ssum[w] = s;
    *(float4*)(&sr[w][lane * 4]) = r4;
    __syncthreads();

    if (tid < C) {
        float stot = 0.0f, rc = 0.0f;
#pragma unroll
        for (int i = 0; i < 8; i++) { stot += ssum[i]; rc += sr[i][tid]; }
        float val = rc / (stot + 1e-16f);
        out[(size_t)b * 4 * C + iter * C + tid] = val;       // readout
        __nv_bfloat16 hv = __float2bfloat16(val);            // r splits for next GEMM
        XhO[(size_t)b * 256 + C + tid] = hv;
        XlO[(size_t)b * 256 + C + tid] = __float2bfloat16(val - __bfloat162float(hv));
    }
}

// ---------------- launch -----------------------------------------------------
extern "C" void kernel_launch(void* const* d_in, const int* in_sizes, int n_in,
                              void* d_out, int out_size) {
    const float* k     = (const float*)d_in[0];
    const float* v     = (const float*)d_in[1];
    const float* h     = (const float*)d_in[2];
    const float* W_ih  = (const float*)d_in[3];
    const float* W_hh  = (const float*)d_in[4];
    const float* b_ih  = (const float*)d_in[5];
    const float* b_hh  = (const float*)d_in[6];
    const int*   batch = (const int*)d_in[7];
    float* out = (float*)d_out;

    int N = in_sizes[0] / C;
    int B = in_sizes[2] / C;

    cudaFuncSetAttribute(gemm_fused, cudaFuncAttributeMaxDynamicSharedMemorySize, DYN_BYTES);

    int prep_items = (B * C > N + 1) ? B * C : N + 1;   // covers 512*256 too
    prep_all<<<(prep_items + 255) / 256, 256>>>(W_ih, W_hh, b_ih, b_hh, h, batch, N, B);

    for (int t = 0; t < 4; t++) {
        int cur = t & 1, nxt = (t + 1) & 1;
        gemm_fused<<<dim3(8, B / 64), 128, DYN_BYTES>>>(
            h, t == 0 ? 1 : 0, t == 0 ? 4 : 8, cur, nxt);
        attn_kernel<<<B, 256>>>(k, v, out, t, nxt);
    }
}